// round 1
// baseline (speedup 1.0000x reference)
#include <cuda_runtime.h>
#include <math.h>

// Problem constants
#define CC 10000
#define KK 4
#define DD 2048
#define ROWS (CC * KK)        // 40000
#define WARPS_PER_BLOCK 8
#define THREADS (WARPS_PER_BLOCK * 32)
#define GRID (ROWS / WARPS_PER_BLOCK)  // 5000

// Scratch: per-prototype squared distances (allocation-free rule -> device global)
__device__ float g_d[ROWS];

// Kernel 1: one warp per prototype row. Feature staged in smem.
__global__ __launch_bounds__(THREADS) void dist_kernel(
    const float* __restrict__ feat,
    const float* __restrict__ protos)
{
    __shared__ float sf[DD];
    for (int i = threadIdx.x; i < DD; i += THREADS)
        sf[i] = feat[i];
    __syncthreads();

    const int warp = threadIdx.x >> 5;
    const int lane = threadIdx.x & 31;
    const int row  = blockIdx.x * WARPS_PER_BLOCK + warp;

    const float4* __restrict__ p = (const float4*)(protos + (size_t)row * DD);
    const float4* __restrict__ f = (const float4*)sf;

    float acc = 0.0f;
    // D=2048 floats = 512 float4; warp covers 32 float4 per iter -> 16 iters
    #pragma unroll
    for (int it = 0; it < DD / 128; ++it) {
        float4 pv = p[it * 32 + lane];
        float4 fv = f[it * 32 + lane];
        float dx = pv.x - fv.x;
        float dy = pv.y - fv.y;
        float dz = pv.z - fv.z;
        float dw = pv.w - fv.w;
        acc = fmaf(dx, dx, acc);
        acc = fmaf(dy, dy, acc);
        acc = fmaf(dz, dz, acc);
        acc = fmaf(dw, dw, acc);
    }

    // warp reduction
    #pragma unroll
    for (int o = 16; o > 0; o >>= 1)
        acc += __shfl_xor_sync(0xffffffffu, acc, o);

    if (lane == 0)
        g_d[row] = acc;
}

// Kernel 2: single block online logsumexp over g_d + label-row sum -> scalar out.
__global__ __launch_bounds__(1024) void reduce_kernel(
    const int* __restrict__ label,
    float* __restrict__ out)
{
    __shared__ float sm_m[32];
    __shared__ float sm_s[32];

    float m = -INFINITY;
    float s = 0.0f;

    for (int i = threadIdx.x; i < ROWS; i += 1024) {
        float l = -g_d[i];           // logits = -gamma*d, gamma=1
        if (l > m) {
            s = s * expf(m - l) + 1.0f;
            m = l;
        } else {
            s += expf(l - m);
        }
    }

    // warp-level combine of (m, s)
    #pragma unroll
    for (int o = 16; o > 0; o >>= 1) {
        float om = __shfl_xor_sync(0xffffffffu, m, o);
        float os = __shfl_xor_sync(0xffffffffu, s, o);
        float M = fmaxf(m, om);
        // guard against -inf - -inf
        float e1 = (m == -INFINITY) ? 0.0f : expf(m - M);
        float e2 = (om == -INFINITY) ? 0.0f : expf(om - M);
        s = s * e1 + os * e2;
        m = M;
    }

    const int warp = threadIdx.x >> 5;
    const int lane = threadIdx.x & 31;
    if (lane == 0) { sm_m[warp] = m; sm_s[warp] = s; }
    __syncthreads();

    if (warp == 0) {
        m = sm_m[lane];
        s = sm_s[lane];
        #pragma unroll
        for (int o = 16; o > 0; o >>= 1) {
            float om = __shfl_xor_sync(0xffffffffu, m, o);
            float os = __shfl_xor_sync(0xffffffffu, s, o);
            float M = fmaxf(m, om);
            float e1 = (m == -INFINITY) ? 0.0f : expf(m - M);
            float e2 = (om == -INFINITY) ? 0.0f : expf(om - M);
            s = s * e1 + os * e2;
            m = M;
        }
        if (lane == 0) {
            float log_one = m + logf(s);
            int lbl = *label;
            float lblsum = 0.0f;
            #pragma unroll
            for (int k = 0; k < KK; ++k)
                lblsum += g_d[lbl * KK + k];
            // probability = sum_k (log_one - logits[label,k]) = K*log_one + sum_k d[label,k]
            out[0] = (float)KK * log_one + lblsum;
        }
    }
}

extern "C" void kernel_launch(void* const* d_in, const int* in_sizes, int n_in,
                              void* d_out, int out_size)
{
    const float* feat   = (const float*)d_in[0];
    const int*   label  = (const int*)d_in[1];
    const float* protos = (const float*)d_in[2];
    float* out = (float*)d_out;

    dist_kernel<<<GRID, THREADS>>>(feat, protos);
    reduce_kernel<<<1, 1024>>>(label, out);
}

// round 2
// speedup vs baseline: 1.1101x; 1.1101x over previous
#include <cuda_runtime.h>
#include <math.h>

// Problem constants
#define CC 10000
#define KK 4
#define DD 2048
#define ROWS (CC * KK)        // 40000
#define WARPS_PER_BLOCK 8
#define THREADS (WARPS_PER_BLOCK * 32)
#define GRID (ROWS / WARPS_PER_BLOCK)  // 5000 blocks, one (m,s) partial each

// Scratch (allocation-free rule -> device globals)
__device__ float g_pm[GRID];     // per-block max logit
__device__ float g_ps[GRID];     // per-block sum exp(logit - m)
__device__ float g_lbl[KK];      // d[label, k]

// Kernel 1: one warp per prototype row; per-block logsumexp partial.
__global__ __launch_bounds__(THREADS) void dist_kernel(
    const float* __restrict__ feat,
    const int*  __restrict__ label,
    const float* __restrict__ protos)
{
    __shared__ float sf[DD];
    __shared__ float sd[WARPS_PER_BLOCK];

    for (int i = threadIdx.x; i < DD; i += THREADS)
        sf[i] = feat[i];
    __syncthreads();

    const int warp = threadIdx.x >> 5;
    const int lane = threadIdx.x & 31;
    const int row  = blockIdx.x * WARPS_PER_BLOCK + warp;

    const float4* __restrict__ p = (const float4*)(protos + (size_t)row * DD);
    const float4* __restrict__ f = (const float4*)sf;

    float acc = 0.0f;
    // D=2048 floats = 512 float4; warp covers 32 float4 per iter -> 16 iters
    #pragma unroll
    for (int it = 0; it < DD / 128; ++it) {
        float4 pv = p[it * 32 + lane];
        float4 fv = f[it * 32 + lane];
        float dx = pv.x - fv.x;
        float dy = pv.y - fv.y;
        float dz = pv.z - fv.z;
        float dw = pv.w - fv.w;
        acc = fmaf(dx, dx, acc);
        acc = fmaf(dy, dy, acc);
        acc = fmaf(dz, dz, acc);
        acc = fmaf(dw, dw, acc);
    }

    // warp reduction -> full squared distance for this row
    #pragma unroll
    for (int o = 16; o > 0; o >>= 1)
        acc += __shfl_xor_sync(0xffffffffu, acc, o);

    if (lane == 0) {
        sd[warp] = acc;
        // label-row side channel (tiny)
        if ((row >> 2) == *label)          // row / KK
            g_lbl[row & 3] = acc;          // row % KK
    }
    __syncthreads();

    // Warp 0 combines the 8 row distances into one (m, s) partial.
    if (warp == 0) {
        float l = (lane < WARPS_PER_BLOCK) ? -sd[lane] : -INFINITY;
        float m = l;
        #pragma unroll
        for (int o = 4; o > 0; o >>= 1)
            m = fmaxf(m, __shfl_xor_sync(0xffffffffu, m, o));
        // lanes 0..7 now all hold the max over the 8
        float e = (lane < WARPS_PER_BLOCK) ? expf(l - m) : 0.0f;
        #pragma unroll
        for (int o = 4; o > 0; o >>= 1)
            e += __shfl_xor_sync(0xffffffffu, e, o);
        if (lane == 0) {
            g_pm[blockIdx.x] = m;
            g_ps[blockIdx.x] = e;
        }
    }
}

// Kernel 2: combine 5000 (m,s) partials in one block; emit the scalar.
__global__ __launch_bounds__(1024) void reduce_kernel(float* __restrict__ out)
{
    __shared__ float sm_m[32];
    __shared__ float sm_s[32];

    float m = -INFINITY;
    float s = 0.0f;

    for (int i = threadIdx.x; i < GRID; i += 1024) {
        float pm = g_pm[i];
        float ps = g_ps[i];
        float M = fmaxf(m, pm);
        float e1 = (m  == -INFINITY) ? 0.0f : expf(m  - M);
        float e2 = (pm == -INFINITY) ? 0.0f : expf(pm - M);
        s = s * e1 + ps * e2;
        m = M;
    }

    #pragma unroll
    for (int o = 16; o > 0; o >>= 1) {
        float om = __shfl_xor_sync(0xffffffffu, m, o);
        float os = __shfl_xor_sync(0xffffffffu, s, o);
        float M = fmaxf(m, om);
        float e1 = (m  == -INFINITY) ? 0.0f : expf(m  - M);
        float e2 = (om == -INFINITY) ? 0.0f : expf(om - M);
        s = s * e1 + os * e2;
        m = M;
    }

    const int warp = threadIdx.x >> 5;
    const int lane = threadIdx.x & 31;
    if (lane == 0) { sm_m[warp] = m; sm_s[warp] = s; }
    __syncthreads();

    if (warp == 0) {
        m = sm_m[lane];
        s = sm_s[lane];
        #pragma unroll
        for (int o = 16; o > 0; o >>= 1) {
            float om = __shfl_xor_sync(0xffffffffu, m, o);
            float os = __shfl_xor_sync(0xffffffffu, s, o);
            float M = fmaxf(m, om);
            float e1 = (m  == -INFINITY) ? 0.0f : expf(m  - M);
            float e2 = (om == -INFINITY) ? 0.0f : expf(om - M);
            s = s * e1 + os * e2;
            m = M;
        }
        if (lane == 0) {
            float log_one = m + logf(s);
            float lblsum = g_lbl[0] + g_lbl[1] + g_lbl[2] + g_lbl[3];
            // probability = sum_k (log_one - logits[label,k]) = K*log_one + sum_k d[label,k]
            out[0] = (float)KK * log_one + lblsum;
        }
    }
}

extern "C" void kernel_launch(void* const* d_in, const int* in_sizes, int n_in,
                              void* d_out, int out_size)
{
    const float* feat   = (const float*)d_in[0];
    const int*   label  = (const int*)d_in[1];
    const float* protos = (const float*)d_in[2];
    float* out = (float*)d_out;

    dist_kernel<<<GRID, THREADS>>>(feat, label, protos);
    reduce_kernel<<<1, 1024>>>(out);
}

// round 3
// speedup vs baseline: 1.1482x; 1.0343x over previous
#include <cuda_runtime.h>
#include <math.h>

// Problem constants
#define CC 10000
#define KK 4
#define DD 2048
#define ROWS (CC * KK)           // 40000
#define WARPS_PER_BLOCK 32
#define THREADS (WARPS_PER_BLOCK * 32)   // 1024
#define GRID (ROWS / WARPS_PER_BLOCK)    // 1250 blocks, one (m,s) partial each

// Scratch (allocation-free rule -> device globals)
__device__ float g_pm[GRID];          // per-block max logit
__device__ float g_ps[GRID];          // per-block sum exp(logit - m)
__device__ float g_lbl[KK];           // d[label, k]
__device__ unsigned int g_ticket;     // completion counter (self-resetting)

__global__ __launch_bounds__(THREADS) void fused_kernel(
    const float* __restrict__ feat,
    const int*  __restrict__ label,
    const float* __restrict__ protos,
    float* __restrict__ out)
{
    __shared__ float sf[DD];
    __shared__ float sd[WARPS_PER_BLOCK];
    __shared__ float sred[32];
    __shared__ float s_bcast;
    __shared__ int s_islast;

    // stage feature (8 KB) in smem with float4 loads
    {
        float4* sf4 = (float4*)sf;
        const float4* f4 = (const float4*)feat;
        if (threadIdx.x < DD / 4)
            sf4[threadIdx.x] = f4[threadIdx.x];
    }
    __syncthreads();

    const int warp = threadIdx.x >> 5;
    const int lane = threadIdx.x & 31;
    const int row  = blockIdx.x * WARPS_PER_BLOCK + warp;

    const float4* __restrict__ p = (const float4*)(protos + (size_t)row * DD);
    const float4* __restrict__ f = (const float4*)sf;

    float acc = 0.0f;
    // D=2048 floats = 512 float4; warp covers 32 float4 per iter -> 16 iters
    #pragma unroll
    for (int it = 0; it < DD / 128; ++it) {
        float4 pv = p[it * 32 + lane];
        float4 fv = f[it * 32 + lane];
        float dx = pv.x - fv.x;
        float dy = pv.y - fv.y;
        float dz = pv.z - fv.z;
        float dw = pv.w - fv.w;
        acc = fmaf(dx, dx, acc);
        acc = fmaf(dy, dy, acc);
        acc = fmaf(dz, dz, acc);
        acc = fmaf(dw, dw, acc);
    }

    // warp reduction -> full squared distance for this row
    #pragma unroll
    for (int o = 16; o > 0; o >>= 1)
        acc += __shfl_xor_sync(0xffffffffu, acc, o);

    if (lane == 0) {
        sd[warp] = acc;
        if ((row >> 2) == *label)          // row / KK
            g_lbl[row & 3] = acc;          // row % KK
    }
    __syncthreads();

    // Warp 0 combines the 32 row distances into one (m, s) partial.
    if (warp == 0) {
        float l = -sd[lane];
        float m = l;
        #pragma unroll
        for (int o = 16; o > 0; o >>= 1)
            m = fmaxf(m, __shfl_xor_sync(0xffffffffu, m, o));
        float e = expf(l - m);
        #pragma unroll
        for (int o = 16; o > 0; o >>= 1)
            e += __shfl_xor_sync(0xffffffffu, e, o);
        if (lane == 0) {
            g_pm[blockIdx.x] = m;
            g_ps[blockIdx.x] = e;
        }
    }

    // ---- last-block-done final reduction ----
    if (threadIdx.x == 0) {
        __threadfence();   // make g_pm/g_ps/g_lbl visible before ticket
        unsigned int t = atomicAdd(&g_ticket, 1u);
        s_islast = (t == (unsigned int)(GRID - 1));
    }
    __syncthreads();
    if (!s_islast) return;

    // This (last) block reduces all GRID=1250 partials. Deterministic:
    // fixed array, fixed tree order, independent of which block runs it.
    const int tid = threadIdx.x;

    // phase 0: load partials into registers (independent loads)
    float m0 = -INFINITY, s0 = 0.0f, m1 = -INFINITY, s1 = 0.0f;
    if (tid < GRID)          { m0 = g_pm[tid];          s0 = g_ps[tid]; }
    if (tid + 1024 < GRID)   { m1 = g_pm[tid + 1024];   s1 = g_ps[tid + 1024]; }

    // phase 1: global max (cheap fmaxf tree, no exp dependency)
    float mloc = fmaxf(m0, m1);
    #pragma unroll
    for (int o = 16; o > 0; o >>= 1)
        mloc = fmaxf(mloc, __shfl_xor_sync(0xffffffffu, mloc, o));
    if (lane == 0) sred[warp] = mloc;
    __syncthreads();
    if (warp == 0) {
        float v = sred[lane];
        #pragma unroll
        for (int o = 16; o > 0; o >>= 1)
            v = fmaxf(v, __shfl_xor_sync(0xffffffffu, v, o));
        if (lane == 0) s_bcast = v;
    }
    __syncthreads();
    const float M = s_bcast;

    // phase 2: sum with independent exps (exp(-inf - M) = 0, s=0 -> 0, safe)
    float sloc = s0 * expf(m0 - M) + s1 * expf(m1 - M);
    #pragma unroll
    for (int o = 16; o > 0; o >>= 1)
        sloc += __shfl_xor_sync(0xffffffffu, sloc, o);
    if (lane == 0) sred[warp] = sloc;
    __syncthreads();
    if (warp == 0) {
        float v = sred[lane];
        #pragma unroll
        for (int o = 16; o > 0; o >>= 1)
            v += __shfl_xor_sync(0xffffffffu, v, o);
        if (lane == 0) {
            float log_one = M + logf(v);
            float lblsum = g_lbl[0] + g_lbl[1] + g_lbl[2] + g_lbl[3];
            // probability = sum_k (log_one - logits[label,k]) = K*log_one + sum_k d[label,k]
            out[0] = (float)KK * log_one + lblsum;
            g_ticket = 0u;   // reset for next graph replay
        }
    }
}

extern "C" void kernel_launch(void* const* d_in, const int* in_sizes, int n_in,
                              void* d_out, int out_size)
{
    const float* feat   = (const float*)d_in[0];
    const int*   label  = (const int*)d_in[1];
    const float* protos = (const float*)d_in[2];
    float* out = (float*)d_out;

    fused_kernel<<<GRID, THREADS>>>(feat, label, protos, out);
}